// round 12
// baseline (speedup 1.0000x reference)
#include <cuda_runtime.h>
#include <cuda_fp16.h>
#include <cstdint>

#define NN   12288
#define KK   32
#define DD   128

typedef unsigned long long ull;

// Scratch: G = raw_features @ W_lin^T, fp16 (N x 128, 3.15 MB)
__device__ __align__(16) __half g_Gh[NN * DD];
// Scratch: masked gather weights w[b][k] (1.5 MB)
__device__ __align__(16) float  g_w[NN * KK];

// ---------------------------------------------------------------------------
// packed f32x2 helpers
// ---------------------------------------------------------------------------
__device__ __forceinline__ ull pack_dup(float x) {
    ull r;
    asm("mov.b64 %0, {%1, %1};" : "=l"(r) : "f"(x));
    return r;
}
__device__ __forceinline__ void fma2(ull& d, ull a, ull b) {
    asm("fma.rn.f32x2 %0, %1, %2, %0;" : "+l"(d) : "l"(a), "l"(b));
}
__device__ __forceinline__ void unpack2(float& lo, float& hi, ull v) {
    asm("mov.b64 {%0, %1}, %2;" : "=f"(lo), "=f"(hi) : "l"(v));
}

// ---------------------------------------------------------------------------
// Kernel A (side stream): w-prep, max TLP. 1536 blocks x 256 thr.
// Pure random-DRAM latency work (3% issue) — overlaps with the GEMM kernel
// via the graph DAG; the HW scheduler backfills SMs from both kernels.
// ---------------------------------------------------------------------------
__global__ void __launch_bounds__(256)
wprep_kernel(const int* __restrict__ nodes,
             const int* __restrict__ neighbors,
             const float* __restrict__ rew)
{
    const int e    = blockIdx.x * 256 + threadIdx.x;   // entry = b*32 + k
    const int node = __ldg(&nodes[e >> 5]);            // broadcast in warp
    const int nb   = __ldg(&neighbors[e]);             // coalesced
    float w = 0.0f;
    if (nb != node)
        w = __ldg(&rew[(size_t)node * NN + nb]);       // random access
    g_w[e] = w;                                        // coalesced
}

// ---------------------------------------------------------------------------
// Kernel B (main stream, concurrent with A): GEMM G = F @ W^T (fp16 out).
// Grid (192,2): 64x64 tiles, 128 threads, 3 CTAs/SM. FFMA2 microtile 8x4.
// ---------------------------------------------------------------------------
__global__ void __launch_bounds__(128, 3)
gemm_G_kernel(const float* __restrict__ F, const float* __restrict__ W)
{
    extern __shared__ float sm[];
    float* Fst = sm;                 // 128 * 66  (Fst[k*66 + m])
    float* Wt  = sm + 128 * 66;      // 128 * 66  (Wt [k*66 + n])

    const int tid = threadIdx.x;
    const int bm  = blockIdx.x;
    const int bn  = blockIdx.y;

    const float* Fblk = F + (size_t)bm * 64 * DD;
    const float* Wblk = W + (size_t)bn * 64 * DD;

    #pragma unroll 8
    for (int idx = tid; idx < 64 * 128; idx += 128) {
        int r = idx >> 7, k = idx & 127;
        Fst[k * 66 + r] = Fblk[idx];
        Wt [k * 66 + r] = Wblk[idx];
    }
    __syncthreads();

    const int tx = tid & 15;   // cols 4*tx .. 4*tx+3
    const int ty = tid >> 4;   // rows 8*ty .. 8*ty+7

    ull acc[4][4];
    #pragma unroll
    for (int p = 0; p < 4; p++)
        #pragma unroll
        for (int c = 0; c < 4; c++)
            acc[p][c] = 0ULL;

    #pragma unroll 4
    for (int kk = 0; kk < 128; kk++) {
        const float* fr = &Fst[kk * 66 + 8 * ty];
        ull a2[4];
        #pragma unroll
        for (int p = 0; p < 4; p++)
            a2[p] = *reinterpret_cast<const ull*>(&fr[2 * p]);

        float2 b01 = *reinterpret_cast<const float2*>(&Wt[kk * 66 + 4 * tx]);
        float2 b23 = *reinterpret_cast<const float2*>(&Wt[kk * 66 + 4 * tx + 2]);
        ull bd[4];
        bd[0] = pack_dup(b01.x); bd[1] = pack_dup(b01.y);
        bd[2] = pack_dup(b23.x); bd[3] = pack_dup(b23.y);

        #pragma unroll
        for (int p = 0; p < 4; p++)
            #pragma unroll
            for (int c = 0; c < 4; c++)
                fma2(acc[p][c], a2[p], bd[c]);
    }

    float v[8][4];
    #pragma unroll
    for (int p = 0; p < 4; p++)
        #pragma unroll
        for (int c = 0; c < 4; c++) {
            float lo, hi;
            unpack2(lo, hi, acc[p][c]);
            v[2 * p][c]     = lo;
            v[2 * p + 1][c] = hi;
        }

    const int gm0 = bm * 64 + 8 * ty;
    const int gn0 = bn * 64 + 4 * tx;
    #pragma unroll
    for (int r = 0; r < 8; r++) {
        __half2 h01 = __floats2half2_rn(v[r][0], v[r][1]);
        __half2 h23 = __floats2half2_rn(v[r][2], v[r][3]);
        uint2 st;
        st.x = *reinterpret_cast<unsigned*>(&h01);
        st.y = *reinterpret_cast<unsigned*>(&h23);
        *reinterpret_cast<uint2*>(&g_Gh[(size_t)(gm0 + r) * DD + gn0]) = st;
    }
}

// ---------------------------------------------------------------------------
// Kernel C: out[b][d] = relu( sum_k w[b][k] * G[nb[b][k]][d] + bias[d] )
// 256 thr = 16 nodes/block; warp handles 2 nodes (lanes 0-15 / 16-31),
// lane owns 8 fp16 cols (one LDG.128 per k). w precomputed (coalesced).
// Accumulate in packed f32x2.
// ---------------------------------------------------------------------------
__global__ void __launch_bounds__(256)
gather_kernel(const int* __restrict__ neighbors,
              const float* __restrict__ b_lin,
              float* __restrict__ out)
{
    __shared__ int   nb_s[16][KK];
    __shared__ float w_s [16][KK];

    const int tid = threadIdx.x;
    const int b0  = blockIdx.x * 16;

    #pragma unroll
    for (int i = 0; i < 2; i++) {
        const int e  = tid + i * 256;
        const int ln = e >> 5;
        const int k  = e & 31;
        const int gi = (b0 + ln) * KK + k;
        nb_s[ln][k] = neighbors[gi];
        w_s [ln][k] = g_w[gi];
    }
    __syncthreads();

    const int lane = tid & 31;
    const int ln2  = ((tid >> 5) << 1) | (lane >> 4);  // local node 0..15
    const int col  = (lane & 15) * 8;                  // 8 cols per lane
    const int b    = b0 + ln2;

    ull acc[4];
    #pragma unroll
    for (int i = 0; i < 4; i++) acc[i] = 0ULL;

    #pragma unroll
    for (int kb = 0; kb < KK; kb += 4) {
        uint4 g[4];
        float wv[4];
        #pragma unroll
        for (int u = 0; u < 4; u++) {
            const int nb = nb_s[ln2][kb + u];
            wv[u] = w_s[ln2][kb + u];
            g[u]  = __ldg(reinterpret_cast<const uint4*>(
                              &g_Gh[(size_t)nb * DD + col]));
        }
        #pragma unroll
        for (int u = 0; u < 4; u++) {
            const ull wd = pack_dup(wv[u]);
            float2 f0 = __half22float2(*reinterpret_cast<__half2*>(&g[u].x));
            float2 f1 = __half22float2(*reinterpret_cast<__half2*>(&g[u].y));
            float2 f2 = __half22float2(*reinterpret_cast<__half2*>(&g[u].z));
            float2 f3 = __half22float2(*reinterpret_cast<__half2*>(&g[u].w));
            fma2(acc[0], wd, *reinterpret_cast<ull*>(&f0));
            fma2(acc[1], wd, *reinterpret_cast<ull*>(&f1));
            fma2(acc[2], wd, *reinterpret_cast<ull*>(&f2));
            fma2(acc[3], wd, *reinterpret_cast<ull*>(&f3));
        }
    }

    float a[8];
    #pragma unroll
    for (int i = 0; i < 4; i++) unpack2(a[2 * i], a[2 * i + 1], acc[i]);

    const float4 bias0 = __ldg(reinterpret_cast<const float4*>(&b_lin[col]));
    const float4 bias1 = __ldg(reinterpret_cast<const float4*>(&b_lin[col + 4]));
    float4 o0, o1;
    o0.x = fmaxf(a[0] + bias0.x, 0.f);
    o0.y = fmaxf(a[1] + bias0.y, 0.f);
    o0.z = fmaxf(a[2] + bias0.z, 0.f);
    o0.w = fmaxf(a[3] + bias0.w, 0.f);
    o1.x = fmaxf(a[4] + bias1.x, 0.f);
    o1.y = fmaxf(a[5] + bias1.y, 0.f);
    o1.z = fmaxf(a[6] + bias1.z, 0.f);
    o1.w = fmaxf(a[7] + bias1.w, 0.f);
    float* op = &out[(size_t)b * DD + col];
    *reinterpret_cast<float4*>(op)     = o0;
    *reinterpret_cast<float4*>(op + 4) = o1;
}

// ---------------------------------------------------------------------------
// Launch: fork/join DAG so wprep (DRAM-bound) and GEMM (issue-bound) run
// CONCURRENTLY as two kernels. Streams/events created lazily on the first
// (uncaptured correctness) call; the captured graph contains the fork/join
// edges. No allocs, no syncs — capture-legal.
//
// Inputs: nodes(i32 N), neighbors(i32 N*K), raw_features(f32 N*128),
//         reweighted(f32 N*N), W_lin(f32 128*128), b_lin(f32 128)
// ---------------------------------------------------------------------------
extern "C" void kernel_launch(void* const* d_in, const int* in_sizes, int n_in,
                              void* d_out, int out_size)
{
    const int*   nodes      = (const int*)  d_in[0];
    const int*   neighbors  = (const int*)  d_in[1];
    const float* raw_feats  = (const float*)d_in[2];
    const float* reweighted = (const float*)d_in[3];
    const float* W_lin      = (const float*)d_in[4];
    const float* b_lin      = (const float*)d_in[5];
    float*       out        = (float*)d_out;

    const int smem = 2 * 128 * 66 * (int)sizeof(float);  // 67584 B

    static cudaStream_t s_side = nullptr;
    static cudaEvent_t  e_fork = nullptr, e_join = nullptr;
    if (s_side == nullptr) {
        cudaStreamCreateWithFlags(&s_side, cudaStreamNonBlocking);
        cudaEventCreateWithFlags(&e_fork, cudaEventDisableTiming);
        cudaEventCreateWithFlags(&e_join, cudaEventDisableTiming);
        cudaFuncSetAttribute(gemm_G_kernel,
                             cudaFuncAttributeMaxDynamicSharedMemorySize, smem);
    }

    // fork: side stream joins the capture DAG
    cudaEventRecord(e_fork, 0);
    cudaStreamWaitEvent(s_side, e_fork, 0);

    // A: w-prep on side stream (DRAM-bound, 3% issue)
    wprep_kernel<<<NN * KK / 256, 256, 0, s_side>>>(nodes, neighbors, reweighted);
    cudaEventRecord(e_join, s_side);

    // B: GEMM on main stream (issue-bound) — concurrent with A
    dim3 ggrid(NN / 64, DD / 64);
    gemm_G_kernel<<<ggrid, 128, smem>>>(raw_feats, W_lin);

    // join: gather needs both g_w (A) and g_Gh (B)
    cudaStreamWaitEvent(0, e_join, 0);
    gather_kernel<<<NN / 16, 256>>>(neighbors, b_lin, out);
}

// round 13
// speedup vs baseline: 1.0237x; 1.0237x over previous
#include <cuda_runtime.h>
#include <cuda_fp16.h>
#include <cstdint>

#define NN   12288
#define KK   32
#define DD   128

typedef unsigned long long ull;

// Scratch: G = raw_features @ W_lin^T, fp16 (N x 128, 3.15 MB)
__device__ __align__(16) __half g_Gh[NN * DD];
// Scratch: masked gather weights w[b][k] (1.5 MB)
__device__ __align__(16) float  g_w[NN * KK];

// ---------------------------------------------------------------------------
// packed f32x2 helpers
// ---------------------------------------------------------------------------
__device__ __forceinline__ ull pack_dup(float x) {
    ull r;
    asm("mov.b64 %0, {%1, %1};" : "=l"(r) : "f"(x));
    return r;
}
__device__ __forceinline__ void fma2(ull& d, ull a, ull b) {
    asm("fma.rn.f32x2 %0, %1, %2, %0;" : "+l"(d) : "l"(a), "l"(b));
}
__device__ __forceinline__ void unpack2(float& lo, float& hi, ull v) {
    asm("mov.b64 {%0, %1}, %2;" : "=f"(lo), "=f"(hi) : "l"(v));
}

// ---------------------------------------------------------------------------
// Kernel A (side stream): w-prep, SMALL residency footprint so it co-resides
// with the GEMM. 384 blocks x 256 thr x 4 entries/thread (MLP-4) = all 393K
// random rew loads in flight from ~666 threads/SM, 0 smem, 16 regs.
// DRAM-random bound (~14us); ~3% issue usage.
// ---------------------------------------------------------------------------
#define WP_STRIDE (384 * 256)
__global__ void __launch_bounds__(256)
wprep_kernel(const int* __restrict__ nodes,
             const int* __restrict__ neighbors,
             const float* __restrict__ rew)
{
    const int e0 = blockIdx.x * 256 + threadIdx.x;

    int nd4[4], nb4[4];
    #pragma unroll
    for (int i = 0; i < 4; i++) {
        const int e = e0 + i * WP_STRIDE;
        nd4[i] = __ldg(&nodes[e >> 5]);        // warp-broadcast
        nb4[i] = __ldg(&neighbors[e]);         // coalesced
    }
    float w4[4];
    #pragma unroll
    for (int i = 0; i < 4; i++) {
        float w = 0.0f;
        if (nb4[i] != nd4[i])
            w = __ldg(&rew[(size_t)nd4[i] * NN + nb4[i]]);  // random line
        w4[i] = w;
    }
    #pragma unroll
    for (int i = 0; i < 4; i++)
        g_w[e0 + i * WP_STRIDE] = w4[i];       // coalesced
}

// ---------------------------------------------------------------------------
// Kernel B (main stream, concurrent with A): GEMM G = F @ W^T (fp16 out).
// Grid (192,2): 64x64 tiles, 128 threads, 3 CTAs/SM. FFMA2 microtile 8x4.
// ---------------------------------------------------------------------------
__global__ void __launch_bounds__(128, 3)
gemm_G_kernel(const float* __restrict__ F, const float* __restrict__ W)
{
    extern __shared__ float sm[];
    float* Fst = sm;                 // 128 * 66  (Fst[k*66 + m])
    float* Wt  = sm + 128 * 66;      // 128 * 66  (Wt [k*66 + n])

    const int tid = threadIdx.x;
    const int bm  = blockIdx.x;
    const int bn  = blockIdx.y;

    const float* Fblk = F + (size_t)bm * 64 * DD;
    const float* Wblk = W + (size_t)bn * 64 * DD;

    #pragma unroll 8
    for (int idx = tid; idx < 64 * 128; idx += 128) {
        int r = idx >> 7, k = idx & 127;
        Fst[k * 66 + r] = Fblk[idx];
        Wt [k * 66 + r] = Wblk[idx];
    }
    __syncthreads();

    const int tx = tid & 15;   // cols 4*tx .. 4*tx+3
    const int ty = tid >> 4;   // rows 8*ty .. 8*ty+7

    ull acc[4][4];
    #pragma unroll
    for (int p = 0; p < 4; p++)
        #pragma unroll
        for (int c = 0; c < 4; c++)
            acc[p][c] = 0ULL;

    #pragma unroll 4
    for (int kk = 0; kk < 128; kk++) {
        const float* fr = &Fst[kk * 66 + 8 * ty];
        ull a2[4];
        #pragma unroll
        for (int p = 0; p < 4; p++)
            a2[p] = *reinterpret_cast<const ull*>(&fr[2 * p]);

        float2 b01 = *reinterpret_cast<const float2*>(&Wt[kk * 66 + 4 * tx]);
        float2 b23 = *reinterpret_cast<const float2*>(&Wt[kk * 66 + 4 * tx + 2]);
        ull bd[4];
        bd[0] = pack_dup(b01.x); bd[1] = pack_dup(b01.y);
        bd[2] = pack_dup(b23.x); bd[3] = pack_dup(b23.y);

        #pragma unroll
        for (int p = 0; p < 4; p++)
            #pragma unroll
            for (int c = 0; c < 4; c++)
                fma2(acc[p][c], a2[p], bd[c]);
    }

    float v[8][4];
    #pragma unroll
    for (int p = 0; p < 4; p++)
        #pragma unroll
        for (int c = 0; c < 4; c++) {
            float lo, hi;
            unpack2(lo, hi, acc[p][c]);
            v[2 * p][c]     = lo;
            v[2 * p + 1][c] = hi;
        }

    const int gm0 = bm * 64 + 8 * ty;
    const int gn0 = bn * 64 + 4 * tx;
    #pragma unroll
    for (int r = 0; r < 8; r++) {
        __half2 h01 = __floats2half2_rn(v[r][0], v[r][1]);
        __half2 h23 = __floats2half2_rn(v[r][2], v[r][3]);
        uint2 st;
        st.x = *reinterpret_cast<unsigned*>(&h01);
        st.y = *reinterpret_cast<unsigned*>(&h23);
        *reinterpret_cast<uint2*>(&g_Gh[(size_t)(gm0 + r) * DD + gn0]) = st;
    }
}

// ---------------------------------------------------------------------------
// Kernel C: out[b][d] = relu( sum_k w[b][k] * G[nb[b][k]][d] + bias[d] )
// 256 thr = 16 nodes/block; warp handles 2 nodes (lanes 0-15 / 16-31),
// lane owns 8 fp16 cols (one LDG.128 per k). w precomputed (coalesced).
// Accumulate in packed f32x2.
// ---------------------------------------------------------------------------
__global__ void __launch_bounds__(256)
gather_kernel(const int* __restrict__ neighbors,
              const float* __restrict__ b_lin,
              float* __restrict__ out)
{
    __shared__ int   nb_s[16][KK];
    __shared__ float w_s [16][KK];

    const int tid = threadIdx.x;
    const int b0  = blockIdx.x * 16;

    #pragma unroll
    for (int i = 0; i < 2; i++) {
        const int e  = tid + i * 256;
        const int ln = e >> 5;
        const int k  = e & 31;
        const int gi = (b0 + ln) * KK + k;
        nb_s[ln][k] = neighbors[gi];
        w_s [ln][k] = g_w[gi];
    }
    __syncthreads();

    const int lane = tid & 31;
    const int ln2  = ((tid >> 5) << 1) | (lane >> 4);  // local node 0..15
    const int col  = (lane & 15) * 8;                  // 8 cols per lane
    const int b    = b0 + ln2;

    ull acc[4];
    #pragma unroll
    for (int i = 0; i < 4; i++) acc[i] = 0ULL;

    #pragma unroll
    for (int kb = 0; kb < KK; kb += 4) {
        uint4 g[4];
        float wv[4];
        #pragma unroll
        for (int u = 0; u < 4; u++) {
            const int nb = nb_s[ln2][kb + u];
            wv[u] = w_s[ln2][kb + u];
            g[u]  = __ldg(reinterpret_cast<const uint4*>(
                              &g_Gh[(size_t)nb * DD + col]));
        }
        #pragma unroll
        for (int u = 0; u < 4; u++) {
            const ull wd = pack_dup(wv[u]);
            float2 f0 = __half22float2(*reinterpret_cast<__half2*>(&g[u].x));
            float2 f1 = __half22float2(*reinterpret_cast<__half2*>(&g[u].y));
            float2 f2 = __half22float2(*reinterpret_cast<__half2*>(&g[u].z));
            float2 f3 = __half22float2(*reinterpret_cast<__half2*>(&g[u].w));
            fma2(acc[0], wd, *reinterpret_cast<ull*>(&f0));
            fma2(acc[1], wd, *reinterpret_cast<ull*>(&f1));
            fma2(acc[2], wd, *reinterpret_cast<ull*>(&f2));
            fma2(acc[3], wd, *reinterpret_cast<ull*>(&f3));
        }
    }

    float a[8];
    #pragma unroll
    for (int i = 0; i < 4; i++) unpack2(a[2 * i], a[2 * i + 1], acc[i]);

    const float4 bias0 = __ldg(reinterpret_cast<const float4*>(&b_lin[col]));
    const float4 bias1 = __ldg(reinterpret_cast<const float4*>(&b_lin[col + 4]));
    float4 o0, o1;
    o0.x = fmaxf(a[0] + bias0.x, 0.f);
    o0.y = fmaxf(a[1] + bias0.y, 0.f);
    o0.z = fmaxf(a[2] + bias0.z, 0.f);
    o0.w = fmaxf(a[3] + bias0.w, 0.f);
    o1.x = fmaxf(a[4] + bias1.x, 0.f);
    o1.y = fmaxf(a[5] + bias1.y, 0.f);
    o1.z = fmaxf(a[6] + bias1.z, 0.f);
    o1.w = fmaxf(a[7] + bias1.w, 0.f);
    float* op = &out[(size_t)b * DD + col];
    *reinterpret_cast<float4*>(op)     = o0;
    *reinterpret_cast<float4*>(op + 4) = o1;
}

// ---------------------------------------------------------------------------
// Launch: parallel DAG (GEMM on main stream, small-footprint wprep on side
// stream). Both kernels are now RESOURCE-compatible: per SM ~2.6 wprep CTAs
// (666 thr, 0 smem) + ~2.6 GEMM CTAs (333 thr, 175KB smem) => truly
// co-resident, HW scheduler interleaves issue-bound + DRAM-bound work.
//
// Inputs: nodes(i32 N), neighbors(i32 N*K), raw_features(f32 N*128),
//         reweighted(f32 N*N), W_lin(f32 128*128), b_lin(f32 128)
// ---------------------------------------------------------------------------
extern "C" void kernel_launch(void* const* d_in, const int* in_sizes, int n_in,
                              void* d_out, int out_size)
{
    const int*   nodes      = (const int*)  d_in[0];
    const int*   neighbors  = (const int*)  d_in[1];
    const float* raw_feats  = (const float*)d_in[2];
    const float* reweighted = (const float*)d_in[3];
    const float* W_lin      = (const float*)d_in[4];
    const float* b_lin      = (const float*)d_in[5];
    float*       out        = (float*)d_out;

    const int smem = 2 * 128 * 66 * (int)sizeof(float);  // 67584 B

    static cudaStream_t s_side = nullptr;
    static cudaEvent_t  e_fork = nullptr, e_join = nullptr;
    if (s_side == nullptr) {
        cudaStreamCreateWithFlags(&s_side, cudaStreamNonBlocking);
        cudaEventCreateWithFlags(&e_fork, cudaEventDisableTiming);
        cudaEventCreateWithFlags(&e_join, cudaEventDisableTiming);
        cudaFuncSetAttribute(gemm_G_kernel,
                             cudaFuncAttributeMaxDynamicSharedMemorySize, smem);
    }

    // fork side stream into the DAG
    cudaEventRecord(e_fork, 0);
    cudaStreamWaitEvent(s_side, e_fork, 0);

    // B: GEMM on main stream (issue-bound, 384 CTAs, big smem)
    dim3 ggrid(NN / 64, DD / 64);
    gemm_G_kernel<<<ggrid, 128, smem>>>(raw_feats, W_lin);

    // A: w-prep on side stream (DRAM-bound, small footprint) — concurrent
    wprep_kernel<<<NN * KK / (256 * 4), 256, 0, s_side>>>(nodes, neighbors,
                                                          reweighted);
    cudaEventRecord(e_join, s_side);

    // join: gather needs both g_w (A) and g_Gh (B)
    cudaStreamWaitEvent(0, e_join, 0);
    gather_kernel<<<NN / 16, 256>>>(neighbors, b_lin, out);
}

// round 14
// speedup vs baseline: 1.2685x; 1.2391x over previous
#include <cuda_runtime.h>
#include <cuda_fp16.h>
#include <cstdint>

#define NN   12288
#define KK   32
#define DD   128

typedef unsigned long long ull;

// Scratch: G = raw_features @ W_lin^T, fp16 (N x 128, 3.15 MB)
__device__ __align__(16) __half g_Gh[NN * DD];

// ---------------------------------------------------------------------------
// helpers
// ---------------------------------------------------------------------------
__device__ __forceinline__ ull pack_dup(float x) {
    ull r;
    asm("mov.b64 %0, {%1, %1};" : "=l"(r) : "f"(x));
    return r;
}
__device__ __forceinline__ void fma2(ull& d, ull a, ull b) {
    asm("fma.rn.f32x2 %0, %1, %2, %0;" : "+l"(d) : "l"(a), "l"(b));
}
__device__ __forceinline__ void unpack2(float& lo, float& hi, ull v) {
    asm("mov.b64 {%0, %1}, %2;" : "=f"(lo), "=f"(hi) : "l"(v));
}
__device__ __forceinline__ unsigned smem_u32(const void* p) {
    unsigned r;
    asm("{ .reg .u64 t; cvta.to.shared.u64 t, %1; cvt.u32.u64 %0, t; }"
        : "=r"(r) : "l"(p));
    return r;
}

// ---------------------------------------------------------------------------
// Kernel 1: G = F @ W^T via tensor cores (mma.sync.m16n8k16, f16 in/f32 acc,
// fp16 out). 96 CTAs (single wave) x 256 thr (8 warps); CTA = 128 rows x 128
// cols x K=128. Warp w owns rows 16w..16w+15.
//   Ah [r][k]  fp16, pad 136 halfs/row  (ldmatrix row source, conflict-free:
//              row stride 272B ≡ 4 words mod 32)
//   Bh [k][n]  fp16 TRANSPOSED W, pad 136 (ldmatrix.trans source for B frag)
// ---------------------------------------------------------------------------
__global__ void __launch_bounds__(256)
gemm_hmma_kernel(const float* __restrict__ F, const float* __restrict__ W)
{
    extern __shared__ __half sh[];
    __half* Ah = sh;                  // [128][136]
    __half* Bh = sh + 128 * 136;      // [128][136]   Bh[k][n] = W[n][k]

    const int tid = threadIdx.x;
    const int bm  = blockIdx.x;
    const float* Fblk = F + (size_t)bm * 128 * DD;

    // ---- stage A: f32 -> f16, coalesced float4 loads, 8B smem stores ----
    #pragma unroll
    for (int i = 0; i < 16; i++) {
        const int flat = (tid + i * 256) * 4;
        const int r = flat >> 7, c = flat & 127;
        const float4 v = *reinterpret_cast<const float4*>(&Fblk[flat]);
        __half2 h0 = __floats2half2_rn(v.x, v.y);
        __half2 h1 = __floats2half2_rn(v.z, v.w);
        uint2 st;
        st.x = *reinterpret_cast<unsigned*>(&h0);
        st.y = *reinterpret_cast<unsigned*>(&h1);
        *reinterpret_cast<uint2*>(&Ah[r * 136 + c]) = st;
    }
    // ---- stage B transposed: Bh[k][n] = W[n][k] ----
    #pragma unroll
    for (int i = 0; i < 16; i++) {
        const int flat = (tid + i * 256) * 4;
        const int n = flat >> 7, k = flat & 127;
        const float4 v = *reinterpret_cast<const float4*>(&W[flat]);
        Bh[(k + 0) * 136 + n] = __float2half_rn(v.x);
        Bh[(k + 1) * 136 + n] = __float2half_rn(v.y);
        Bh[(k + 2) * 136 + n] = __float2half_rn(v.z);
        Bh[(k + 3) * 136 + n] = __float2half_rn(v.w);
    }
    __syncthreads();

    const int wid  = tid >> 5;
    const int lane = tid & 31;
    const int m0   = wid * 16;

    float acc[16][4];
    #pragma unroll
    for (int j = 0; j < 16; j++)
        #pragma unroll
        for (int t = 0; t < 4; t++)
            acc[j][t] = 0.0f;

    const unsigned aAddr0 = smem_u32(Ah);
    const unsigned bAddr0 = smem_u32(Bh);
    const int l15 = lane & 15;

    #pragma unroll
    for (int kc = 0; kc < 8; kc++) {
        const int k0 = kc * 16;
        // A frag: lanes 0-7 rows 0-7 k0..7 | 8-15 rows 8-15 | 16-23 rows0-7 k+8 | 24-31 rows8-15 k+8
        unsigned pa = aAddr0 +
            ((m0 + l15) * 136 + k0 + ((lane >> 4) << 3)) * 2;
        unsigned a0, a1, a2, a3;
        asm volatile("ldmatrix.sync.aligned.m8n8.x4.shared.b16 {%0,%1,%2,%3}, [%4];"
                     : "=r"(a0), "=r"(a1), "=r"(a2), "=r"(a3) : "r"(pa));

        #pragma unroll
        for (int j = 0; j < 16; j++) {
            // B frag: lanes 0-15 address rows k0..k0+15 of Bh, cols 8j..8j+7
            unsigned pb = bAddr0 + ((k0 + l15) * 136 + 8 * j) * 2;
            unsigned b0, b1;
            asm volatile("ldmatrix.sync.aligned.m8n8.x2.trans.shared.b16 {%0,%1}, [%2];"
                         : "=r"(b0), "=r"(b1) : "r"(pb));
            asm volatile(
                "mma.sync.aligned.m16n8k16.row.col.f32.f16.f16.f32 "
                "{%0,%1,%2,%3}, {%4,%5,%6,%7}, {%8,%9}, {%0,%1,%2,%3};"
                : "+f"(acc[j][0]), "+f"(acc[j][1]),
                  "+f"(acc[j][2]), "+f"(acc[j][3])
                : "r"(a0), "r"(a1), "r"(a2), "r"(a3), "r"(b0), "r"(b1));
        }
    }

    // ---- epilogue: D frag -> fp16 G. d0/d1: row=lane>>2, col=2*(lane&3);
    //      d2/d3: row+8. half2 stores. ----
    const int grow = bm * 128 + m0 + (lane >> 2);
    const int coff = (lane & 3) * 2;
    #pragma unroll
    for (int j = 0; j < 16; j++) {
        __half2 lo = __floats2half2_rn(acc[j][0], acc[j][1]);
        __half2 hi = __floats2half2_rn(acc[j][2], acc[j][3]);
        *reinterpret_cast<__half2*>(&g_Gh[(size_t)grow * DD + 8 * j + coff]) = lo;
        *reinterpret_cast<__half2*>(&g_Gh[(size_t)(grow + 8) * DD + 8 * j + coff]) = hi;
    }
}

// ---------------------------------------------------------------------------
// Kernel 2 (fused): w-prep prologue + gather.
// 768 blocks x 256 thr = 16 nodes/block, 8 CTAs/SM co-resident.
// Prologue: each thread stages 2 (nb, w) entries — the 2 random rew loads are
// independent and issued back-to-back; barrier waits overlap ACROSS the 8
// resident blocks. Body: warp = 2 nodes, lane owns 8 fp16 cols (LDG.128),
// packed f32x2 accumulate.
// ---------------------------------------------------------------------------
__global__ void __launch_bounds__(256)
gather_fused_kernel(const int* __restrict__ nodes,
                    const int* __restrict__ neighbors,
                    const float* __restrict__ rew,
                    const float* __restrict__ b_lin,
                    float* __restrict__ out)
{
    __shared__ int   nb_s[16][KK];
    __shared__ float w_s [16][KK];

    const int tid = threadIdx.x;
    const int b0  = blockIdx.x * 16;

    // ---- inline w-prep: 512 entries, 2/thread, random loads batched ----
    {
        const int e0 = tid, e1 = tid + 256;
        const int b_a = b0 + (e0 >> 5), k_a = e0 & 31;
        const int b_b = b0 + (e1 >> 5), k_b = e1 & 31;
        const int nd_a = __ldg(&nodes[b_a]);
        const int nd_b = __ldg(&nodes[b_b]);
        const int nb_a = __ldg(&neighbors[b_a * KK + k_a]);
        const int nb_b = __ldg(&neighbors[b_b * KK + k_b]);
        float w_a = 0.0f, w_b = 0.0f;
        if (nb_a != nd_a) w_a = __ldg(&rew[(size_t)nd_a * NN + nb_a]);
        if (nb_b != nd_b) w_b = __ldg(&rew[(size_t)nd_b * NN + nb_b]);
        nb_s[e0 >> 5][k_a] = nb_a;  w_s[e0 >> 5][k_a] = w_a;
        nb_s[e1 >> 5][k_b] = nb_b;  w_s[e1 >> 5][k_b] = w_b;
    }
    __syncthreads();

    const int lane = tid & 31;
    const int ln2  = ((tid >> 5) << 1) | (lane >> 4);  // local node 0..15
    const int col  = (lane & 15) * 8;                  // 8 cols per lane
    const int b    = b0 + ln2;

    ull acc[4];
    #pragma unroll
    for (int i = 0; i < 4; i++) acc[i] = 0ULL;

    #pragma unroll
    for (int kb = 0; kb < KK; kb += 4) {
        uint4 g[4];
        float wv[4];
        #pragma unroll
        for (int u = 0; u < 4; u++) {
            const int nb = nb_s[ln2][kb + u];
            wv[u] = w_s[ln2][kb + u];
            g[u]  = __ldg(reinterpret_cast<const uint4*>(
                              &g_Gh[(size_t)nb * DD + col]));
        }
        #pragma unroll
        for (int u = 0; u < 4; u++) {
            const ull wd = pack_dup(wv[u]);
            float2 f0 = __half22float2(*reinterpret_cast<__half2*>(&g[u].x));
            float2 f1 = __half22float2(*reinterpret_cast<__half2*>(&g[u].y));
            float2 f2 = __half22float2(*reinterpret_cast<__half2*>(&g[u].z));
            float2 f3 = __half22float2(*reinterpret_cast<__half2*>(&g[u].w));
            fma2(acc[0], wd, *reinterpret_cast<ull*>(&f0));
            fma2(acc[1], wd, *reinterpret_cast<ull*>(&f1));
            fma2(acc[2], wd, *reinterpret_cast<ull*>(&f2));
            fma2(acc[3], wd, *reinterpret_cast<ull*>(&f3));
        }
    }

    float a[8];
    #pragma unroll
    for (int i = 0; i < 4; i++) unpack2(a[2 * i], a[2 * i + 1], acc[i]);

    const float4 bias0 = __ldg(reinterpret_cast<const float4*>(&b_lin[col]));
    const float4 bias1 = __ldg(reinterpret_cast<const float4*>(&b_lin[col + 4]));
    float4 o0, o1;
    o0.x = fmaxf(a[0] + bias0.x, 0.f);
    o0.y = fmaxf(a[1] + bias0.y, 0.f);
    o0.z = fmaxf(a[2] + bias0.z, 0.f);
    o0.w = fmaxf(a[3] + bias0.w, 0.f);
    o1.x = fmaxf(a[4] + bias1.x, 0.f);
    o1.y = fmaxf(a[5] + bias1.y, 0.f);
    o1.z = fmaxf(a[6] + bias1.z, 0.f);
    o1.w = fmaxf(a[7] + bias1.w, 0.f);
    float* op = &out[(size_t)b * DD + col];
    *reinterpret_cast<float4*>(op)     = o0;
    *reinterpret_cast<float4*>(op + 4) = o1;
}

// ---------------------------------------------------------------------------
// Launch. Inputs: nodes(i32 N), neighbors(i32 N*K), raw_features(f32 N*128),
//                 reweighted(f32 N*N), W_lin(f32 128*128), b_lin(f32 128)
// ---------------------------------------------------------------------------
extern "C" void kernel_launch(void* const* d_in, const int* in_sizes, int n_in,
                              void* d_out, int out_size)
{
    const int*   nodes      = (const int*)  d_in[0];
    const int*   neighbors  = (const int*)  d_in[1];
    const float* raw_feats  = (const float*)d_in[2];
    const float* reweighted = (const float*)d_in[3];
    const float* W_lin      = (const float*)d_in[4];
    const float* b_lin      = (const float*)d_in[5];
    float*       out        = (float*)d_out;

    const int smem = 2 * 128 * 136 * (int)sizeof(__half);  // 69632 B
    static bool attr_set = false;
    if (!attr_set) {
        cudaFuncSetAttribute(gemm_hmma_kernel,
                             cudaFuncAttributeMaxDynamicSharedMemorySize, smem);
        attr_set = true;
    }

    gemm_hmma_kernel<<<NN / 128, 256, smem>>>(raw_feats, W_lin);
    gather_fused_kernel<<<NN / 16, 256>>>(nodes, neighbors, reweighted,
                                          b_lin, out);
}